// round 1
// baseline (speedup 1.0000x reference)
#include <cuda_runtime.h>
#include <cuda_bf16.h>
#include <math.h>

// ---------------- Problem constants ----------------
#define BATCH 4
#define SEQ   2048
#define T_TOT (BATCH*SEQ)      // 8192
#define D_MODEL 768
#define L_LAYERS 4
#define N_STATE 16
#define K_CONV  4
#define I_INNER 1536           // 2*D_MODEL
#define DT_RANK 48
#define VOCAB 32000
#define EPS 1e-5f

// ---------------- Scratch (static device globals; no allocs) ----------------
__device__ float g_h   [(size_t)T_TOT * D_MODEL];    // residual stream
__device__ float g_x   [(size_t)T_TOT * D_MODEL];    // rmsnorm output
__device__ float g_proj[(size_t)T_TOT * 2 * I_INNER];// in_proj out: [u | gate]
__device__ float g_ut  [(size_t)T_TOT * I_INNER];    // conv+silu output
__device__ float g_xdbl[(size_t)T_TOT * 80];         // [dt_r(48) | B(16) | C(16)]
__device__ float g_dt  [(size_t)T_TOT * I_INNER];    // softplus dt
__device__ float g_y   [(size_t)T_TOT * I_INNER];    // scan output (gated)
__device__ float g_hn  [BATCH * D_MODEL];            // final-normed last tokens

// ---------------- Embedding gather ----------------
__global__ void gather_kernel(const int* __restrict__ ids,
                              const float* __restrict__ embed,
                              float* __restrict__ h) {
    int t = blockIdx.x;            // 0..8191
    int c = threadIdx.x;           // 0..191 (float4 lanes: 192*4=768)
    int id = ids[t];
    const float4* src = (const float4*)(embed + (size_t)id * D_MODEL);
    float4* dst = (float4*)(h + (size_t)t * D_MODEL);
    dst[c] = src[c];
}

// ---------------- RMSNorm (per row of 768) ----------------
__global__ void rmsnorm_kernel(const float* __restrict__ x, long in_stride,
                               const float* __restrict__ w,
                               float* __restrict__ y, long out_stride) {
    long r = blockIdx.x;
    const float* xr = x + r * in_stride;
    float* yr = y + r * out_stride;
    int tid = threadIdx.x; // 256
    float v0 = xr[tid], v1 = xr[tid + 256], v2 = xr[tid + 512];
    float s = v0 * v0 + v1 * v1 + v2 * v2;
    #pragma unroll
    for (int o = 16; o; o >>= 1) s += __shfl_xor_sync(0xffffffffu, s, o);
    __shared__ float ws[8];
    __shared__ float sc;
    if ((tid & 31) == 0) ws[tid >> 5] = s;
    __syncthreads();
    if (tid == 0) {
        float tsum = 0.f;
        #pragma unroll
        for (int k = 0; k < 8; k++) tsum += ws[k];
        sc = rsqrtf(tsum * (1.0f / D_MODEL) + EPS);
    }
    __syncthreads();
    float scale = sc;
    yr[tid]       = v0 * scale * w[tid];
    yr[tid + 256] = v1 * scale * w[tid + 256];
    yr[tid + 512] = v2 * scale * w[tid + 512];
}

// ---------------- SGEMM: C[m,n] = sum_k A[m,k]*B[n,k]  (A MxK rm, B NxK rm) ----
// M fixed = 8192 (gridDim.y*128). N,K runtime with K%8==0, lda/ldb/ldc %4==0.
// EPI: 0 = store, 1 = C += acc (residual), 2 = C = softplus(acc + bias[n])
__device__ __forceinline__ float softplusf(float v) {
    return (v > 20.f) ? v : log1pf(__expf(v));
}

template<int EPI>
__global__ __launch_bounds__(256)
void sgemm_nt(const float* __restrict__ A, int lda,
              const float* __restrict__ B, int ldb,
              float* __restrict__ C, int ldc,
              int N, int K, const float* __restrict__ bias) {
    __shared__ float As[8][128];
    __shared__ float Bs[8][128];
    int tid = threadIdx.x;
    int m0 = blockIdx.y * 128, n0 = blockIdx.x * 128;
    int lrow = tid >> 1;          // 0..127
    int lk   = (tid & 1) * 4;     // 0 or 4
    const float* Ap = A + (size_t)(m0 + lrow) * lda + lk;
    int brow = n0 + lrow;
    bool bvalid = brow < N;
    const float* Bp = B + (size_t)(bvalid ? brow : (N - 1)) * ldb + lk;
    int rbase = (tid >> 4) * 8;
    int cbase = (tid & 15) * 8;

    float acc[8][8];
    #pragma unroll
    for (int i = 0; i < 8; i++)
        #pragma unroll
        for (int j = 0; j < 8; j++) acc[i][j] = 0.f;

    float4 av = *(const float4*)(Ap);
    float4 bv = bvalid ? *(const float4*)(Bp) : make_float4(0.f, 0.f, 0.f, 0.f);

    for (int kt = 0; kt < K; kt += 8) {
        As[lk + 0][lrow] = av.x; As[lk + 1][lrow] = av.y;
        As[lk + 2][lrow] = av.z; As[lk + 3][lrow] = av.w;
        Bs[lk + 0][lrow] = bv.x; Bs[lk + 1][lrow] = bv.y;
        Bs[lk + 2][lrow] = bv.z; Bs[lk + 3][lrow] = bv.w;
        __syncthreads();
        if (kt + 8 < K) {  // register prefetch of next tile
            av = *(const float4*)(Ap + kt + 8);
            bv = bvalid ? *(const float4*)(Bp + kt + 8) : make_float4(0.f,0.f,0.f,0.f);
        }
        #pragma unroll
        for (int kk = 0; kk < 8; kk++) {
            float a[8], b8[8];
            #pragma unroll
            for (int i = 0; i < 8; i++) a[i] = As[kk][rbase + i];
            #pragma unroll
            for (int j = 0; j < 8; j++) b8[j] = Bs[kk][cbase + j];
            #pragma unroll
            for (int i = 0; i < 8; i++)
                #pragma unroll
                for (int j = 0; j < 8; j++)
                    acc[i][j] = fmaf(a[i], b8[j], acc[i][j]);
        }
        __syncthreads();
    }

    #pragma unroll
    for (int i = 0; i < 8; i++) {
        size_t off = (size_t)(m0 + rbase + i) * ldc + n0 + cbase;
        #pragma unroll
        for (int jj = 0; jj < 8; jj += 4) {
            int ncol = n0 + cbase + jj;
            if (ncol < N) {
                float4 v = make_float4(acc[i][jj], acc[i][jj+1], acc[i][jj+2], acc[i][jj+3]);
                if (EPI == 1) {
                    float4 old = *(float4*)(C + off + jj);
                    v.x += old.x; v.y += old.y; v.z += old.z; v.w += old.w;
                } else if (EPI == 2) {
                    float4 bb = *(const float4*)(bias + ncol);
                    v.x = softplusf(v.x + bb.x); v.y = softplusf(v.y + bb.y);
                    v.z = softplusf(v.z + bb.z); v.w = softplusf(v.w + bb.w);
                }
                *(float4*)(C + off + jj) = v;
            }
        }
    }
}

// ---------------- Depthwise causal conv (K=4) + bias + SiLU ----------------
__global__ void conv_silu_kernel(const float* __restrict__ proj,
                                 const float* __restrict__ cw,
                                 const float* __restrict__ cb,
                                 float* __restrict__ ut) {
    long idx = (long)blockIdx.x * 256 + threadIdx.x;
    if (idx >= (long)T_TOT * I_INNER) return;
    int i = (int)(idx % I_INNER);
    long t = idx / I_INNER;
    int tl = (int)(t & (SEQ - 1));
    long base = t * (2 * I_INNER) + i;
    float w0 = cw[i*4+0], w1 = cw[i*4+1], w2 = cw[i*4+2], w3 = cw[i*4+3];
    float s = cb[i];
    s = fmaf(w3, proj[base], s);
    if (tl >= 1) s = fmaf(w2, proj[base - 1L*2*I_INNER], s);
    if (tl >= 2) s = fmaf(w1, proj[base - 2L*2*I_INNER], s);
    if (tl >= 3) s = fmaf(w0, proj[base - 3L*2*I_INNER], s);
    float sig = 1.f / (1.f + __expf(-s));
    ut[idx] = s * sig;
}

// ---------------- Selective scan (one thread per (b,i) channel) -----------
// Fused epilogue: y = (scan_y + u*D) * silu(gate)
__global__ void scan_kernel(const float* __restrict__ dt,
                            const float* __restrict__ ut,
                            const float* __restrict__ xdbl,
                            const float* __restrict__ A_log,
                            const float* __restrict__ Dp,
                            const float* __restrict__ proj,
                            float* __restrict__ y) {
    int ch = blockIdx.x * blockDim.x + threadIdx.x;
    if (ch >= BATCH * I_INNER) return;
    int b = ch / I_INNER, i = ch % I_INNER;
    float A[N_STATE], h[N_STATE];
    #pragma unroll
    for (int n = 0; n < N_STATE; n++) {
        A[n] = -__expf(A_log[i * N_STATE + n]);
        h[n] = 0.f;
    }
    float Di = Dp[i];
    const float* dtp = dt   + (size_t)b * SEQ * I_INNER + i;
    const float* up  = ut   + (size_t)b * SEQ * I_INNER + i;
    const float* gp  = proj + (size_t)b * SEQ * 2 * I_INNER + I_INNER + i;
    const float* xp  = xdbl + (size_t)b * SEQ * 80;
    float* yp        = y    + (size_t)b * SEQ * I_INNER + i;

    for (int t = 0; t < SEQ; t++) {
        float d = dtp[(size_t)t * I_INNER];
        float u = up[(size_t)t * I_INNER];
        float du = d * u;
        const float* xr = xp + (size_t)t * 80;
        float acc = 0.f;
        #pragma unroll
        for (int n = 0; n < N_STATE; n++) {
            float Bn = xr[48 + n];
            float Cn = xr[64 + n];
            float dA = __expf(d * A[n]);
            h[n] = fmaf(dA, h[n], du * Bn);
            acc = fmaf(h[n], Cn, acc);
        }
        float g = gp[(size_t)t * 2 * I_INNER];
        float sig = 1.f / (1.f + __expf(-g));
        yp[(size_t)t * I_INNER] = (acc + u * Di) * (g * sig);
    }
}

// ---------------- Logits: out[b,v] = dot(hn[b], embed[v]) ----------------
__global__ void logits_kernel(const float* __restrict__ hn,
                              const float* __restrict__ embed,
                              float* __restrict__ out) {
    __shared__ float sh[BATCH * D_MODEL]; // 12KB
    int tid = threadIdx.x; // 256
    for (int j = tid; j < BATCH * D_MODEL; j += 256) sh[j] = hn[j];
    __syncthreads();
    int warp = tid >> 5, lane = tid & 31;
    int v = blockIdx.x * 8 + warp;
    if (v >= VOCAB) return;
    const float* e = embed + (size_t)v * D_MODEL;
    float a0 = 0.f, a1 = 0.f, a2 = 0.f, a3 = 0.f;
    for (int j = lane; j < D_MODEL; j += 32) {
        float ev = e[j];
        a0 = fmaf(ev, sh[j], a0);
        a1 = fmaf(ev, sh[D_MODEL + j], a1);
        a2 = fmaf(ev, sh[2 * D_MODEL + j], a2);
        a3 = fmaf(ev, sh[3 * D_MODEL + j], a3);
    }
    #pragma unroll
    for (int o = 16; o; o >>= 1) {
        a0 += __shfl_down_sync(0xffffffffu, a0, o);
        a1 += __shfl_down_sync(0xffffffffu, a1, o);
        a2 += __shfl_down_sync(0xffffffffu, a2, o);
        a3 += __shfl_down_sync(0xffffffffu, a3, o);
    }
    if (lane == 0) {
        out[(size_t)0 * VOCAB + v] = a0;
        out[(size_t)1 * VOCAB + v] = a1;
        out[(size_t)2 * VOCAB + v] = a2;
        out[(size_t)3 * VOCAB + v] = a3;
    }
}

// ---------------- Launch ----------------
extern "C" void kernel_launch(void* const* d_in, const int* in_sizes, int n_in,
                              void* d_out, int out_size) {
    const int*   ids       = (const int*)  d_in[0];
    const float* embed     = (const float*)d_in[1];
    const float* norm_w    = (const float*)d_in[2];
    const float* in_proj_w = (const float*)d_in[3];
    const float* conv_w    = (const float*)d_in[4];
    const float* conv_b    = (const float*)d_in[5];
    const float* x_proj_w  = (const float*)d_in[6];
    const float* dt_proj_w = (const float*)d_in[7];
    const float* dt_proj_b = (const float*)d_in[8];
    const float* A_log     = (const float*)d_in[9];
    const float* D_param   = (const float*)d_in[10];
    const float* out_proj_w= (const float*)d_in[11];
    const float* norm_f_w  = (const float*)d_in[12];
    float* out = (float*)d_out;

    float *h, *x, *proj, *ut, *xdbl, *dt, *y, *hn;
    cudaGetSymbolAddress((void**)&h,    g_h);
    cudaGetSymbolAddress((void**)&x,    g_x);
    cudaGetSymbolAddress((void**)&proj, g_proj);
    cudaGetSymbolAddress((void**)&ut,   g_ut);
    cudaGetSymbolAddress((void**)&xdbl, g_xdbl);
    cudaGetSymbolAddress((void**)&dt,   g_dt);
    cudaGetSymbolAddress((void**)&y,    g_y);
    cudaGetSymbolAddress((void**)&hn,   g_hn);

    gather_kernel<<<T_TOT, 192>>>(ids, embed, h);

    for (int l = 0; l < L_LAYERS; l++) {
        // x = rmsnorm(h, norm_w[l])
        rmsnorm_kernel<<<T_TOT, 256>>>(h, D_MODEL, norm_w + l * D_MODEL, x, D_MODEL);
        // proj = x @ in_proj_w[l]^T   (8192 x 3072 x 768)
        sgemm_nt<0><<<dim3(24, 64), 256>>>(x, D_MODEL,
                                           in_proj_w + (size_t)l * 2 * I_INNER * D_MODEL, D_MODEL,
                                           proj, 2 * I_INNER, 2 * I_INNER, D_MODEL, nullptr);
        // ut = silu(conv(u) + cb)
        conv_silu_kernel<<<(T_TOT * I_INNER + 255) / 256, 256>>>(
            proj, conv_w + (size_t)l * I_INNER * K_CONV, conv_b + (size_t)l * I_INNER, ut);
        // xdbl = ut @ x_proj_w[l]^T   (8192 x 80 x 1536)
        sgemm_nt<0><<<dim3(1, 64), 256>>>(ut, I_INNER,
                                          x_proj_w + (size_t)l * 80 * I_INNER, I_INNER,
                                          xdbl, 80, 80, I_INNER, nullptr);
        // dt = softplus(dt_r @ dt_proj_w^T + b)   (8192 x 1536 x 48), A=xdbl lda=80
        sgemm_nt<2><<<dim3(12, 64), 256>>>(xdbl, 80,
                                           dt_proj_w + (size_t)l * I_INNER * DT_RANK, DT_RANK,
                                           dt, I_INNER, I_INNER, DT_RANK,
                                           dt_proj_b + (size_t)l * I_INNER);
        // selective scan + fused (y + u*D)*silu(gate)
        scan_kernel<<<(BATCH * I_INNER + 127) / 128, 128>>>(
            dt, ut, xdbl, A_log + (size_t)l * I_INNER * N_STATE,
            D_param + (size_t)l * I_INNER, proj, y);
        // h += y @ out_proj_w[l]^T    (8192 x 768 x 1536)
        sgemm_nt<1><<<dim3(6, 64), 256>>>(y, I_INNER,
                                          out_proj_w + (size_t)l * D_MODEL * I_INNER, I_INNER,
                                          h, D_MODEL, D_MODEL, I_INNER, nullptr);
    }

    // final rmsnorm on last token of each batch
    rmsnorm_kernel<<<BATCH, 256>>>(h + (size_t)(SEQ - 1) * D_MODEL,
                                   (long)SEQ * D_MODEL, norm_f_w, hn, D_MODEL);
    // logits = hn @ embed^T
    logits_kernel<<<(VOCAB + 7) / 8, 256>>>(hn, embed, out);
}

// round 3
// speedup vs baseline: 1.0037x; 1.0037x over previous
#include <cuda_runtime.h>
#include <cuda_bf16.h>
#include <math.h>
#include <stdint.h>

// ---------------- Problem constants ----------------
#define BATCH 4
#define SEQ   2048
#define T_TOT (BATCH*SEQ)      // 8192
#define D_MODEL 768
#define L_LAYERS 4
#define N_STATE 16
#define K_CONV  4
#define I_INNER 1536           // 2*D_MODEL
#define DT_RANK 48
#define VOCAB 32000
#define EPS 1e-5f

// ---------------- Scratch (static device globals; no allocs) ----------------
__device__ float g_h   [(size_t)T_TOT * D_MODEL];
__device__ float g_x   [(size_t)T_TOT * D_MODEL];
__device__ float g_proj[(size_t)T_TOT * 2 * I_INNER];
__device__ float g_ut  [(size_t)T_TOT * I_INNER];
__device__ float g_xdbl[(size_t)T_TOT * 80];
__device__ float g_dt  [(size_t)T_TOT * I_INNER];
__device__ float g_y   [(size_t)T_TOT * I_INNER];
__device__ float g_hn  [BATCH * D_MODEL];
__device__ float g_wrt [(size_t)2 * I_INNER * D_MODEL];  // rounded-weight scratch (max 3072x768)

// ---------------- small helpers ----------------
__device__ __forceinline__ uint32_t smem_u32(const void* p) {
    uint32_t a;
    asm("{ .reg .u64 t; cvta.to.shared.u64 t, %1; cvt.u32.u64 %0, t; }"
        : "=r"(a) : "l"(p));
    return a;
}
__device__ __forceinline__ float tf32r(float x) {
    uint32_t r;
    asm("cvt.rna.tf32.f32 %0, %1;" : "=r"(r) : "f"(x));
    return __uint_as_float(r);
}
__device__ __forceinline__ void cp_async16(uint32_t dst, const void* src, int sz) {
    asm volatile("cp.async.cg.shared.global [%0], [%1], 16, %2;"
                 :: "r"(dst), "l"(src), "r"(sz) : "memory");
}
#define CP_COMMIT() asm volatile("cp.async.commit_group;" ::: "memory")
#define CP_WAIT2()  asm volatile("cp.async.wait_group 2;" ::: "memory")

__device__ __forceinline__ void mma_tf32(float* d, const uint32_t* a, const uint32_t* b) {
    asm volatile(
        "mma.sync.aligned.m16n8k8.row.col.f32.tf32.tf32.f32 "
        "{%0,%1,%2,%3}, {%4,%5,%6,%7}, {%8,%9}, {%0,%1,%2,%3};"
        : "+f"(d[0]), "+f"(d[1]), "+f"(d[2]), "+f"(d[3])
        : "r"(a[0]), "r"(a[1]), "r"(a[2]), "r"(a[3]), "r"(b[0]), "r"(b[1]));
}

__device__ __forceinline__ float softplusf(float v) {
    return (v > 20.f) ? v : log1pf(__expf(v));
}

// ---------------- tf32 round (weights) ----------------
__global__ void round_tf32_kernel(const float* __restrict__ in,
                                  float* __restrict__ out, int n) {
    int i = blockIdx.x * 256 + threadIdx.x;
    if (i < n) out[i] = tf32r(in[i]);
}

// ================= tensor-core tf32 GEMM (mma.sync m16n8k8) =================
// C[m,n] = sum_k A[m,k]*B[n,k].  A: 8192 x K rm, B: N x K rm (tf32-rounded inputs).
// CTA tile 128x128, 8 warps (4x2), warp tile 32x64, K chunks of 32, 3-stage cp.async.
// EPI: 0 = store, 1 = C += acc, 2 = softplus(acc + bias[n]), 3 = store tf32-rounded.
#define TG_SMEM (6 * 16384)

template<int EPI>
__global__ __launch_bounds__(256)
void tgemm(const float* __restrict__ A, int lda,
           const float* __restrict__ B, int ldb,
           float* __restrict__ C, int ldc,
           int N, int K, const float* __restrict__ bias) {
    extern __shared__ char smem[];
    const uint32_t sbA = smem_u32(smem);
    const uint32_t sbB = sbA + 3 * 16384;

    const int tid = threadIdx.x;
    const int wid = tid >> 5, lane = tid & 31;
    const int warp_m = wid >> 1, warp_n = wid & 1;
    const int r4 = lane >> 2, cc = lane & 3;
    const int m0 = blockIdx.y * 128, n0 = blockIdx.x * 128;
    const int Nvalid = (N - n0 < 128) ? (N - n0) : 128;

    const float* Arow = A + (size_t)m0 * lda;
    const float* Brow = B + (size_t)n0 * ldb;

    const int nc = (K + 31) / 32;

    float acc[2][8][4];
    #pragma unroll
    for (int i = 0; i < 2; i++)
        #pragma unroll
        for (int j = 0; j < 8; j++)
            #pragma unroll
            for (int v = 0; v < 4; v++) acc[i][j][v] = 0.f;

    // per-thread copy assignment: row = tid/2 (0..127), granules (tid&1)*4 + 0..3
    const int crow = tid >> 1;
    const int gb = (tid & 1) * 4;
    const bool bvalid = crow < Nvalid;
    const uint32_t swbase = (uint32_t)crow * 128;

    // ---- issue lambda (macro-style) ----
    #define ISSUE_CHUNK(ch) do {                                            \
        int _st = (ch) % 3;                                                 \
        uint32_t _ab = sbA + _st * 16384;                                   \
        uint32_t _bb = sbB + _st * 16384;                                   \
        int _k0c = (ch) * 32;                                               \
        _Pragma("unroll")                                                   \
        for (int _j = 0; _j < 4; _j++) {                                    \
            int _g = gb + _j;                                               \
            int _k0 = _k0c + _g * 4;                                        \
            int _sz = (K - _k0) * 4;                                        \
            _sz = _sz < 0 ? 0 : (_sz > 16 ? 16 : _sz);                      \
            uint32_t _sw = swbase + ((uint32_t)(_g ^ (crow & 7)) << 4);     \
            const float* _sa = Arow + (size_t)crow * lda + (_sz ? _k0 : 0); \
            cp_async16(_ab + _sw, _sa, _sz);                                \
            int _szb = bvalid ? _sz : 0;                                    \
            const float* _sb = Brow + (_szb ? ((size_t)crow * ldb + _k0) : 0); \
            cp_async16(_bb + _sw, _sb, _szb);                               \
        }                                                                   \
    } while (0)

    ISSUE_CHUNK(0);
    CP_COMMIT();
    if (nc > 1) ISSUE_CHUNK(1);
    CP_COMMIT();

    for (int c = 0; c < nc; c++) {
        if (c + 2 < nc) ISSUE_CHUNK(c + 2);
        CP_COMMIT();
        CP_WAIT2();
        __syncthreads();

        const char* pa = smem + (c % 3) * 16384;
        const char* pb = smem + 3 * 16384 + (c % 3) * 16384;

        #pragma unroll
        for (int ks = 0; ks < 4; ks++) {
            uint32_t afr[2][4];
            uint32_t bfr[8][2];
            const int k = ks * 8 + cc;
            const int gk0 = (k >> 2), gk1 = ((k + 4) >> 2);
            const int kb = (k & 3) * 4;
            #pragma unroll
            for (int am = 0; am < 2; am++) {
                int r0 = warp_m * 32 + am * 16 + r4;
                int r1 = r0 + 8;
                afr[am][0] = *(const uint32_t*)(pa + r0 * 128 + ((gk0 ^ (r0 & 7)) << 4) + kb);
                afr[am][1] = *(const uint32_t*)(pa + r1 * 128 + ((gk0 ^ (r1 & 7)) << 4) + kb);
                afr[am][2] = *(const uint32_t*)(pa + r0 * 128 + ((gk1 ^ (r0 & 7)) << 4) + kb);
                afr[am][3] = *(const uint32_t*)(pa + r1 * 128 + ((gk1 ^ (r1 & 7)) << 4) + kb);
            }
            #pragma unroll
            for (int an = 0; an < 8; an++) {
                int nr = warp_n * 64 + an * 8 + r4;
                bfr[an][0] = *(const uint32_t*)(pb + nr * 128 + ((gk0 ^ (nr & 7)) << 4) + kb);
                bfr[an][1] = *(const uint32_t*)(pb + nr * 128 + ((gk1 ^ (nr & 7)) << 4) + kb);
            }
            #pragma unroll
            for (int am = 0; am < 2; am++)
                #pragma unroll
                for (int an = 0; an < 8; an++)
                    mma_tf32(acc[am][an], afr[am], bfr[an]);
        }
        __syncthreads();
    }

    // ---- epilogue ----
    #pragma unroll
    for (int am = 0; am < 2; am++) {
        #pragma unroll
        for (int p = 0; p < 2; p++) {
            int row = m0 + warp_m * 32 + am * 16 + p * 8 + r4;
            float* crowp = C + (size_t)row * ldc;
            #pragma unroll
            for (int an = 0; an < 8; an++) {
                int col = n0 + warp_n * 64 + an * 8 + cc * 2;
                if (col < N) {
                    float2 v = make_float2(acc[am][an][2 * p], acc[am][an][2 * p + 1]);
                    if (EPI == 1) {
                        float2 o = *(float2*)(crowp + col);
                        v.x += o.x; v.y += o.y;
                    } else if (EPI == 2) {
                        float2 bb2 = *(const float2*)(bias + col);
                        v.x = softplusf(v.x + bb2.x);
                        v.y = softplusf(v.y + bb2.y);
                    } else if (EPI == 3) {
                        v.x = tf32r(v.x); v.y = tf32r(v.y);
                    }
                    *(float2*)(crowp + col) = v;
                }
            }
        }
    }
    #undef ISSUE_CHUNK
}

// ---------------- Embedding gather ----------------
__global__ void gather_kernel(const int* __restrict__ ids,
                              const float* __restrict__ embed,
                              float* __restrict__ h) {
    int t = blockIdx.x;
    int c = threadIdx.x;
    int id = ids[t];
    const float4* src = (const float4*)(embed + (size_t)id * D_MODEL);
    float4* dst = (float4*)(h + (size_t)t * D_MODEL);
    dst[c] = src[c];
}

// ---------------- RMSNorm (per row of 768); optional tf32 rounding -------
__global__ void rmsnorm_kernel(const float* __restrict__ x, long in_stride,
                               const float* __restrict__ w,
                               float* __restrict__ y, long out_stride,
                               int do_round) {
    long r = blockIdx.x;
    const float* xr = x + r * in_stride;
    float* yr = y + r * out_stride;
    int tid = threadIdx.x; // 256
    float v0 = xr[tid], v1 = xr[tid + 256], v2 = xr[tid + 512];
    float s = v0 * v0 + v1 * v1 + v2 * v2;
    #pragma unroll
    for (int o = 16; o; o >>= 1) s += __shfl_xor_sync(0xffffffffu, s, o);
    __shared__ float ws[8];
    __shared__ float sc;
    if ((tid & 31) == 0) ws[tid >> 5] = s;
    __syncthreads();
    if (tid == 0) {
        float tsum = 0.f;
        #pragma unroll
        for (int k = 0; k < 8; k++) tsum += ws[k];
        sc = rsqrtf(tsum * (1.0f / D_MODEL) + EPS);
    }
    __syncthreads();
    float scale = sc;
    float o0 = v0 * scale * w[tid];
    float o1 = v1 * scale * w[tid + 256];
    float o2 = v2 * scale * w[tid + 512];
    if (do_round) { o0 = tf32r(o0); o1 = tf32r(o1); o2 = tf32r(o2); }
    yr[tid] = o0; yr[tid + 256] = o1; yr[tid + 512] = o2;
}

// ---------------- Depthwise causal conv (K=4) + bias + SiLU (tf32 out) ----
__global__ void conv_silu_kernel(const float* __restrict__ proj,
                                 const float* __restrict__ cw,
                                 const float* __restrict__ cb,
                                 float* __restrict__ ut) {
    long idx = (long)blockIdx.x * 256 + threadIdx.x;
    if (idx >= (long)T_TOT * I_INNER) return;
    int i = (int)(idx % I_INNER);
    long t = idx / I_INNER;
    int tl = (int)(t & (SEQ - 1));
    long base = t * (2 * I_INNER) + i;
    float w0 = cw[i*4+0], w1 = cw[i*4+1], w2 = cw[i*4+2], w3 = cw[i*4+3];
    float s = cb[i];
    s = fmaf(w3, proj[base], s);
    if (tl >= 1) s = fmaf(w2, proj[base - 1L*2*I_INNER], s);
    if (tl >= 2) s = fmaf(w1, proj[base - 2L*2*I_INNER], s);
    if (tl >= 3) s = fmaf(w0, proj[base - 3L*2*I_INNER], s);
    float sig = 1.f / (1.f + __expf(-s));
    ut[idx] = tf32r(s * sig);
}

// ---------------- Selective scan (one thread per (b,i) channel) -----------
__global__ void scan_kernel(const float* __restrict__ dt,
                            const float* __restrict__ ut,
                            const float* __restrict__ xdbl,
                            const float* __restrict__ A_log,
                            const float* __restrict__ Dp,
                            const float* __restrict__ proj,
                            float* __restrict__ y) {
    int ch = blockIdx.x * blockDim.x + threadIdx.x;
    if (ch >= BATCH * I_INNER) return;
    int b = ch / I_INNER, i = ch % I_INNER;
    float A[N_STATE], h[N_STATE];
    #pragma unroll
    for (int n = 0; n < N_STATE; n++) {
        A[n] = -__expf(A_log[i * N_STATE + n]);
        h[n] = 0.f;
    }
    float Di = Dp[i];
    const float* dtp = dt   + (size_t)b * SEQ * I_INNER + i;
    const float* up  = ut   + (size_t)b * SEQ * I_INNER + i;
    const float* gp  = proj + (size_t)b * SEQ * 2 * I_INNER + I_INNER + i;
    const float* xp  = xdbl + (size_t)b * SEQ * 80;
    float* yp        = y    + (size_t)b * SEQ * I_INNER + i;

    for (int t = 0; t < SEQ; t++) {
        float d = dtp[(size_t)t * I_INNER];
        float u = up[(size_t)t * I_INNER];
        float du = d * u;
        const float* xr = xp + (size_t)t * 80;
        float acc = 0.f;
        #pragma unroll
        for (int n = 0; n < N_STATE; n++) {
            float Bn = xr[48 + n];
            float Cn = xr[64 + n];
            float dA = __expf(d * A[n]);
            h[n] = fmaf(dA, h[n], du * Bn);
            acc = fmaf(h[n], Cn, acc);
        }
        float g = gp[(size_t)t * 2 * I_INNER];
        float sig = 1.f / (1.f + __expf(-g));
        yp[(size_t)t * I_INNER] = tf32r((acc + u * Di) * (g * sig));
    }
}

// ---------------- Logits: out[b,v] = dot(hn[b], embed[v]) ----------------
__global__ void logits_kernel(const float* __restrict__ hn,
                              const float* __restrict__ embed,
                              float* __restrict__ out) {
    __shared__ float sh[BATCH * D_MODEL];
    int tid = threadIdx.x; // 256
    for (int j = tid; j < BATCH * D_MODEL; j += 256) sh[j] = hn[j];
    __syncthreads();
    int warp = tid >> 5, lane = tid & 31;
    int v = blockIdx.x * 8 + warp;
    if (v >= VOCAB) return;
    const float* e = embed + (size_t)v * D_MODEL;
    float a0 = 0.f, a1 = 0.f, a2 = 0.f, a3 = 0.f;
    for (int j = lane; j < D_MODEL; j += 32) {
        float ev = e[j];
        a0 = fmaf(ev, sh[j], a0);
        a1 = fmaf(ev, sh[D_MODEL + j], a1);
        a2 = fmaf(ev, sh[2 * D_MODEL + j], a2);
        a3 = fmaf(ev, sh[3 * D_MODEL + j], a3);
    }
    #pragma unroll
    for (int o = 16; o; o >>= 1) {
        a0 += __shfl_down_sync(0xffffffffu, a0, o);
        a1 += __shfl_down_sync(0xffffffffu, a1, o);
        a2 += __shfl_down_sync(0xffffffffu, a2, o);
        a3 += __shfl_down_sync(0xffffffffu, a3, o);
    }
    if (lane == 0) {
        out[(size_t)0 * VOCAB + v] = a0;
        out[(size_t)1 * VOCAB + v] = a1;
        out[(size_t)2 * VOCAB + v] = a2;
        out[(size_t)3 * VOCAB + v] = a3;
    }
}

// ---------------- Launch ----------------
extern "C" void kernel_launch(void* const* d_in, const int* in_sizes, int n_in,
                              void* d_out, int out_size) {
    const int*   ids       = (const int*)  d_in[0];
    const float* embed     = (const float*)d_in[1];
    const float* norm_w    = (const float*)d_in[2];
    const float* in_proj_w = (const float*)d_in[3];
    const float* conv_w    = (const float*)d_in[4];
    const float* conv_b    = (const float*)d_in[5];
    const float* x_proj_w  = (const float*)d_in[6];
    const float* dt_proj_w = (const float*)d_in[7];
    const float* dt_proj_b = (const float*)d_in[8];
    const float* A_log     = (const float*)d_in[9];
    const float* D_param   = (const float*)d_in[10];
    const float* out_proj_w= (const float*)d_in[11];
    const float* norm_f_w  = (const float*)d_in[12];
    float* out = (float*)d_out;

    float *h, *x, *proj, *ut, *xdbl, *dt, *y, *hn, *wrt;
    cudaGetSymbolAddress((void**)&h,    g_h);
    cudaGetSymbolAddress((void**)&x,    g_x);
    cudaGetSymbolAddress((void**)&proj, g_proj);
    cudaGetSymbolAddress((void**)&ut,   g_ut);
    cudaGetSymbolAddress((void**)&xdbl, g_xdbl);
    cudaGetSymbolAddress((void**)&dt,   g_dt);
    cudaGetSymbolAddress((void**)&y,    g_y);
    cudaGetSymbolAddress((void**)&hn,   g_hn);
    cudaGetSymbolAddress((void**)&wrt,  g_wrt);

    cudaFuncSetAttribute(tgemm<0>, cudaFuncAttributeMaxDynamicSharedMemorySize, TG_SMEM);
    cudaFuncSetAttribute(tgemm<1>, cudaFuncAttributeMaxDynamicSharedMemorySize, TG_SMEM);
    cudaFuncSetAttribute(tgemm<2>, cudaFuncAttributeMaxDynamicSharedMemorySize, TG_SMEM);
    cudaFuncSetAttribute(tgemm<3>, cudaFuncAttributeMaxDynamicSharedMemorySize, TG_SMEM);

    gather_kernel<<<T_TOT, 192>>>(ids, embed, h);

    for (int l = 0; l < L_LAYERS; l++) {
        // x = tf32(rmsnorm(h))
        rmsnorm_kernel<<<T_TOT, 256>>>(h, D_MODEL, norm_w + l * D_MODEL, x, D_MODEL, 1);

        // proj = x @ in_proj_w^T    (8192 x 3072 x 768)
        {
            int n = 2 * I_INNER * D_MODEL;
            round_tf32_kernel<<<(n + 255) / 256, 256>>>(
                in_proj_w + (size_t)l * n, wrt, n);
            tgemm<0><<<dim3(24, 64), 256, TG_SMEM>>>(
                x, D_MODEL, wrt, D_MODEL, proj, 2 * I_INNER, 2 * I_INNER, D_MODEL, nullptr);
        }

        conv_silu_kernel<<<(T_TOT * I_INNER + 255) / 256, 256>>>(
            proj, conv_w + (size_t)l * I_INNER * K_CONV, conv_b + (size_t)l * I_INNER, ut);

        // xdbl = ut @ x_proj_w^T    (8192 x 80 x 1536), rounded output
        {
            int n = 80 * I_INNER;
            round_tf32_kernel<<<(n + 255) / 256, 256>>>(
                x_proj_w + (size_t)l * n, wrt, n);
            tgemm<3><<<dim3(1, 64), 256, TG_SMEM>>>(
                ut, I_INNER, wrt, I_INNER, xdbl, 80, 80, I_INNER, nullptr);
        }

        // dt = softplus(dt_r @ dt_proj_w^T + b)   (8192 x 1536 x 48)
        {
            int n = I_INNER * DT_RANK;
            round_tf32_kernel<<<(n + 255) / 256, 256>>>(
                dt_proj_w + (size_t)l * n, wrt, n);
            tgemm<2><<<dim3(12, 64), 256, TG_SMEM>>>(
                xdbl, 80, wrt, DT_RANK, dt, I_INNER, I_INNER, DT_RANK,
                dt_proj_b + (size_t)l * I_INNER);
        }

        scan_kernel<<<(BATCH * I_INNER + 127) / 128, 128>>>(
            dt, ut, xdbl, A_log + (size_t)l * I_INNER * N_STATE,
            D_param + (size_t)l * I_INNER, proj, y);

        // h += y @ out_proj_w^T     (8192 x 768 x 1536)
        {
            int n = D_MODEL * I_INNER;
            round_tf32_kernel<<<(n + 255) / 256, 256>>>(
                out_proj_w + (size_t)l * n, wrt, n);
            tgemm<1><<<dim3(6, 64), 256, TG_SMEM>>>(
                y, I_INNER, wrt, I_INNER, h, D_MODEL, D_MODEL, I_INNER, nullptr);
        }
    }

    rmsnorm_kernel<<<BATCH, 256>>>(h + (size_t)(SEQ - 1) * D_MODEL,
                                   (long)SEQ * D_MODEL, norm_f_w, hn, D_MODEL, 0);
    logits_kernel<<<(VOCAB + 7) / 8, 256>>>(hn, embed, out);
}

// round 4
// speedup vs baseline: 4.9167x; 4.8986x over previous
#include <cuda_runtime.h>
#include <cuda_bf16.h>
#include <math.h>
#include <stdint.h>

// ---------------- Problem constants ----------------
#define BATCH 4
#define SEQ   2048
#define T_TOT (BATCH*SEQ)      // 8192
#define D_MODEL 768
#define L_LAYERS 4
#define N_STATE 16
#define K_CONV  4
#define I_INNER 1536           // 2*D_MODEL
#define DT_RANK 48
#define VOCAB 32000
#define EPS 1e-5f

// chunked scan config
#define CH_LEN 128
#define NCHUNK (SEQ / CH_LEN)   // 16

// ---------------- Scratch (static device globals; no allocs) ----------------
__device__ float g_h   [(size_t)T_TOT * D_MODEL];
__device__ float g_x   [(size_t)T_TOT * D_MODEL];
__device__ float g_proj[(size_t)T_TOT * 2 * I_INNER];
__device__ float g_ut  [(size_t)T_TOT * I_INNER];
__device__ float g_xdbl[(size_t)T_TOT * 80];
__device__ float g_dt  [(size_t)T_TOT * I_INNER];
__device__ float g_y   [(size_t)T_TOT * I_INNER];
__device__ float g_hn  [BATCH * D_MODEL];
__device__ float g_wrt [(size_t)2 * I_INNER * D_MODEL];  // rounded-weight scratch
// chunked-scan state: layout [b][c][i][n]
__device__ float g_pA  [(size_t)BATCH * NCHUNK * I_INNER * N_STATE];
__device__ float g_hf  [(size_t)BATCH * NCHUNK * I_INNER * N_STATE];
__device__ float g_hin [(size_t)BATCH * NCHUNK * I_INNER * N_STATE];

// ---------------- small helpers ----------------
__device__ __forceinline__ uint32_t smem_u32(const void* p) {
    uint32_t a;
    asm("{ .reg .u64 t; cvta.to.shared.u64 t, %1; cvt.u32.u64 %0, t; }"
        : "=r"(a) : "l"(p));
    return a;
}
__device__ __forceinline__ float tf32r(float x) {
    uint32_t r;
    asm("cvt.rna.tf32.f32 %0, %1;" : "=r"(r) : "f"(x));
    return __uint_as_float(r);
}
__device__ __forceinline__ void cp_async16(uint32_t dst, const void* src, int sz) {
    asm volatile("cp.async.cg.shared.global [%0], [%1], 16, %2;"
                 :: "r"(dst), "l"(src), "r"(sz) : "memory");
}
#define CP_COMMIT() asm volatile("cp.async.commit_group;" ::: "memory")
#define CP_WAIT2()  asm volatile("cp.async.wait_group 2;" ::: "memory")

__device__ __forceinline__ void mma_tf32(float* d, const uint32_t* a, const uint32_t* b) {
    asm volatile(
        "mma.sync.aligned.m16n8k8.row.col.f32.tf32.tf32.f32 "
        "{%0,%1,%2,%3}, {%4,%5,%6,%7}, {%8,%9}, {%0,%1,%2,%3};"
        : "+f"(d[0]), "+f"(d[1]), "+f"(d[2]), "+f"(d[3])
        : "r"(a[0]), "r"(a[1]), "r"(a[2]), "r"(a[3]), "r"(b[0]), "r"(b[1]));
}

__device__ __forceinline__ float softplusf(float v) {
    return (v > 20.f) ? v : log1pf(__expf(v));
}

// ---------------- tf32 round (weights) ----------------
__global__ void round_tf32_kernel(const float* __restrict__ in,
                                  float* __restrict__ out, int n) {
    int i = blockIdx.x * 256 + threadIdx.x;
    if (i < n) out[i] = tf32r(in[i]);
}

// ================= tensor-core tf32 GEMM (mma.sync m16n8k8) =================
#define TG_SMEM (6 * 16384)

template<int EPI>
__global__ __launch_bounds__(256)
void tgemm(const float* __restrict__ A, int lda,
           const float* __restrict__ B, int ldb,
           float* __restrict__ C, int ldc,
           int N, int K, const float* __restrict__ bias) {
    extern __shared__ char smem[];
    const uint32_t sbA = smem_u32(smem);
    const uint32_t sbB = sbA + 3 * 16384;

    const int tid = threadIdx.x;
    const int wid = tid >> 5, lane = tid & 31;
    const int warp_m = wid >> 1, warp_n = wid & 1;
    const int r4 = lane >> 2, cc = lane & 3;
    const int m0 = blockIdx.y * 128, n0 = blockIdx.x * 128;
    const int Nvalid = (N - n0 < 128) ? (N - n0) : 128;

    const float* Arow = A + (size_t)m0 * lda;
    const float* Brow = B + (size_t)n0 * ldb;

    const int nc = (K + 31) / 32;

    float acc[2][8][4];
    #pragma unroll
    for (int i = 0; i < 2; i++)
        #pragma unroll
        for (int j = 0; j < 8; j++)
            #pragma unroll
            for (int v = 0; v < 4; v++) acc[i][j][v] = 0.f;

    const int crow = tid >> 1;
    const int gb = (tid & 1) * 4;
    const bool bvalid = crow < Nvalid;
    const uint32_t swbase = (uint32_t)crow * 128;

    #define ISSUE_CHUNK(ch) do {                                            \
        int _st = (ch) % 3;                                                 \
        uint32_t _ab = sbA + _st * 16384;                                   \
        uint32_t _bb = sbB + _st * 16384;                                   \
        int _k0c = (ch) * 32;                                               \
        _Pragma("unroll")                                                   \
        for (int _j = 0; _j < 4; _j++) {                                    \
            int _g = gb + _j;                                               \
            int _k0 = _k0c + _g * 4;                                        \
            int _sz = (K - _k0) * 4;                                        \
            _sz = _sz < 0 ? 0 : (_sz > 16 ? 16 : _sz);                      \
            uint32_t _sw = swbase + ((uint32_t)(_g ^ (crow & 7)) << 4);     \
            const float* _sa = Arow + (size_t)crow * lda + (_sz ? _k0 : 0); \
            cp_async16(_ab + _sw, _sa, _sz);                                \
            int _szb = bvalid ? _sz : 0;                                    \
            const float* _sb = Brow + (_szb ? ((size_t)crow * ldb + _k0) : 0); \
            cp_async16(_bb + _sw, _sb, _szb);                               \
        }                                                                   \
    } while (0)

    ISSUE_CHUNK(0);
    CP_COMMIT();
    if (nc > 1) ISSUE_CHUNK(1);
    CP_COMMIT();

    for (int c = 0; c < nc; c++) {
        if (c + 2 < nc) ISSUE_CHUNK(c + 2);
        CP_COMMIT();
        CP_WAIT2();
        __syncthreads();

        const char* pa = smem + (c % 3) * 16384;
        const char* pb = smem + 3 * 16384 + (c % 3) * 16384;

        #pragma unroll
        for (int ks = 0; ks < 4; ks++) {
            uint32_t afr[2][4];
            uint32_t bfr[8][2];
            const int k = ks * 8 + cc;
            const int gk0 = (k >> 2), gk1 = ((k + 4) >> 2);
            const int kb = (k & 3) * 4;
            #pragma unroll
            for (int am = 0; am < 2; am++) {
                int r0 = warp_m * 32 + am * 16 + r4;
                int r1 = r0 + 8;
                afr[am][0] = *(const uint32_t*)(pa + r0 * 128 + ((gk0 ^ (r0 & 7)) << 4) + kb);
                afr[am][1] = *(const uint32_t*)(pa + r1 * 128 + ((gk0 ^ (r1 & 7)) << 4) + kb);
                afr[am][2] = *(const uint32_t*)(pa + r0 * 128 + ((gk1 ^ (r0 & 7)) << 4) + kb);
                afr[am][3] = *(const uint32_t*)(pa + r1 * 128 + ((gk1 ^ (r1 & 7)) << 4) + kb);
            }
            #pragma unroll
            for (int an = 0; an < 8; an++) {
                int nr = warp_n * 64 + an * 8 + r4;
                bfr[an][0] = *(const uint32_t*)(pb + nr * 128 + ((gk0 ^ (nr & 7)) << 4) + kb);
                bfr[an][1] = *(const uint32_t*)(pb + nr * 128 + ((gk1 ^ (nr & 7)) << 4) + kb);
            }
            #pragma unroll
            for (int am = 0; am < 2; am++)
                #pragma unroll
                for (int an = 0; an < 8; an++)
                    mma_tf32(acc[am][an], afr[am], bfr[an]);
        }
        __syncthreads();
    }

    #pragma unroll
    for (int am = 0; am < 2; am++) {
        #pragma unroll
        for (int p = 0; p < 2; p++) {
            int row = m0 + warp_m * 32 + am * 16 + p * 8 + r4;
            float* crowp = C + (size_t)row * ldc;
            #pragma unroll
            for (int an = 0; an < 8; an++) {
                int col = n0 + warp_n * 64 + an * 8 + cc * 2;
                if (col < N) {
                    float2 v = make_float2(acc[am][an][2 * p], acc[am][an][2 * p + 1]);
                    if (EPI == 1) {
                        float2 o = *(float2*)(crowp + col);
                        v.x += o.x; v.y += o.y;
                    } else if (EPI == 2) {
                        float2 bb2 = *(const float2*)(bias + col);
                        v.x = softplusf(v.x + bb2.x);
                        v.y = softplusf(v.y + bb2.y);
                    } else if (EPI == 3) {
                        v.x = tf32r(v.x); v.y = tf32r(v.y);
                    }
                    *(float2*)(crowp + col) = v;
                }
            }
        }
    }
    #undef ISSUE_CHUNK
}

// ---------------- Embedding gather ----------------
__global__ void gather_kernel(const int* __restrict__ ids,
                              const float* __restrict__ embed,
                              float* __restrict__ h) {
    int t = blockIdx.x;
    int c = threadIdx.x;
    int id = ids[t];
    const float4* src = (const float4*)(embed + (size_t)id * D_MODEL);
    float4* dst = (float4*)(h + (size_t)t * D_MODEL);
    dst[c] = src[c];
}

// ---------------- RMSNorm (per row of 768); optional tf32 rounding -------
__global__ void rmsnorm_kernel(const float* __restrict__ x, long in_stride,
                               const float* __restrict__ w,
                               float* __restrict__ y, long out_stride,
                               int do_round) {
    long r = blockIdx.x;
    const float* xr = x + r * in_stride;
    float* yr = y + r * out_stride;
    int tid = threadIdx.x; // 256
    float v0 = xr[tid], v1 = xr[tid + 256], v2 = xr[tid + 512];
    float s = v0 * v0 + v1 * v1 + v2 * v2;
    #pragma unroll
    for (int o = 16; o; o >>= 1) s += __shfl_xor_sync(0xffffffffu, s, o);
    __shared__ float ws[8];
    __shared__ float sc;
    if ((tid & 31) == 0) ws[tid >> 5] = s;
    __syncthreads();
    if (tid == 0) {
        float tsum = 0.f;
        #pragma unroll
        for (int k = 0; k < 8; k++) tsum += ws[k];
        sc = rsqrtf(tsum * (1.0f / D_MODEL) + EPS);
    }
    __syncthreads();
    float scale = sc;
    float o0 = v0 * scale * w[tid];
    float o1 = v1 * scale * w[tid + 256];
    float o2 = v2 * scale * w[tid + 512];
    if (do_round) { o0 = tf32r(o0); o1 = tf32r(o1); o2 = tf32r(o2); }
    yr[tid] = o0; yr[tid + 256] = o1; yr[tid + 512] = o2;
}

// ---------------- Depthwise causal conv (K=4) + bias + SiLU (tf32 out) ----
__global__ void conv_silu_kernel(const float* __restrict__ proj,
                                 const float* __restrict__ cw,
                                 const float* __restrict__ cb,
                                 float* __restrict__ ut) {
    long idx = (long)blockIdx.x * 256 + threadIdx.x;
    if (idx >= (long)T_TOT * I_INNER) return;
    int i = (int)(idx % I_INNER);
    long t = idx / I_INNER;
    int tl = (int)(t & (SEQ - 1));
    long base = t * (2 * I_INNER) + i;
    float w0 = cw[i*4+0], w1 = cw[i*4+1], w2 = cw[i*4+2], w3 = cw[i*4+3];
    float s = cb[i];
    s = fmaf(w3, proj[base], s);
    if (tl >= 1) s = fmaf(w2, proj[base - 1L*2*I_INNER], s);
    if (tl >= 2) s = fmaf(w1, proj[base - 2L*2*I_INNER], s);
    if (tl >= 3) s = fmaf(w0, proj[base - 3L*2*I_INNER], s);
    float sig = 1.f / (1.f + __expf(-s));
    ut[idx] = tf32r(s * sig);
}

// ================= Chunked selective scan =================
// Phase 1: per (b, chunk, i) compute chunk decay product pA[n] and local final
// state hf[n] (starting from h=0).   grid (12, NCHUNK, BATCH) x 128 thr.
__global__ __launch_bounds__(128)
void scan_phase1(const float* __restrict__ dt,
                 const float* __restrict__ ut,
                 const float* __restrict__ xdbl,
                 const float* __restrict__ A_log,
                 float* __restrict__ pA_out,
                 float* __restrict__ hf_out) {
    int i = blockIdx.x * 128 + threadIdx.x;
    int c = blockIdx.y;
    int b = blockIdx.z;
    float A[N_STATE], h[N_STATE], pA[N_STATE];
    #pragma unroll
    for (int n = 0; n < N_STATE; n++) {
        A[n] = -__expf(A_log[i * N_STATE + n]);
        h[n] = 0.f; pA[n] = 1.f;
    }
    int t0 = c * CH_LEN;
    const float* dtp = dt + (size_t)(b * SEQ + t0) * I_INNER + i;
    const float* up  = ut + (size_t)(b * SEQ + t0) * I_INNER + i;
    const float* xp  = xdbl + (size_t)(b * SEQ + t0) * 80;
    for (int t = 0; t < CH_LEN; t++) {
        float d = dtp[(size_t)t * I_INNER];
        float u = up[(size_t)t * I_INNER];
        float du = d * u;
        const float* xr = xp + (size_t)t * 80;
        #pragma unroll
        for (int n = 0; n < N_STATE; n++) {
            float Bn = xr[48 + n];
            float dA = __expf(d * A[n]);
            pA[n] *= dA;
            h[n] = fmaf(dA, h[n], du * Bn);
        }
    }
    size_t off = (size_t)((b * NCHUNK + c) * I_INNER + i) * N_STATE;
    #pragma unroll
    for (int n = 0; n < N_STATE; n++) {
        pA_out[off + n] = pA[n];
        hf_out[off + n] = h[n];
    }
}

// Phase 2: serial combine over chunks per (b,i): hin[c] = incoming state.
__global__ void scan_phase2(const float* __restrict__ pA,
                            const float* __restrict__ hf,
                            float* __restrict__ hin) {
    int ch = blockIdx.x * 128 + threadIdx.x;
    if (ch >= BATCH * I_INNER) return;
    int b = ch / I_INNER, i = ch % I_INNER;
    float h[N_STATE];
    #pragma unroll
    for (int n = 0; n < N_STATE; n++) h[n] = 0.f;
    for (int c = 0; c < NCHUNK; c++) {
        size_t off = (size_t)((b * NCHUNK + c) * I_INNER + i) * N_STATE;
        #pragma unroll
        for (int n = 0; n < N_STATE; n++) {
            hin[off + n] = h[n];
            h[n] = fmaf(pA[off + n], h[n], hf[off + n]);
        }
    }
}

// Phase 3: recompute in-chunk scan from hin, emit y = (acc + u*D)*silu(gate).
__global__ __launch_bounds__(128)
void scan_phase3(const float* __restrict__ dt,
                 const float* __restrict__ ut,
                 const float* __restrict__ xdbl,
                 const float* __restrict__ A_log,
                 const float* __restrict__ Dp,
                 const float* __restrict__ proj,
                 const float* __restrict__ hin,
                 float* __restrict__ y) {
    int i = blockIdx.x * 128 + threadIdx.x;
    int c = blockIdx.y;
    int b = blockIdx.z;
    float A[N_STATE], h[N_STATE];
    size_t soff = (size_t)((b * NCHUNK + c) * I_INNER + i) * N_STATE;
    #pragma unroll
    for (int n = 0; n < N_STATE; n++) {
        A[n] = -__expf(A_log[i * N_STATE + n]);
        h[n] = hin[soff + n];
    }
    float Di = Dp[i];
    int t0 = c * CH_LEN;
    const float* dtp = dt + (size_t)(b * SEQ + t0) * I_INNER + i;
    const float* up  = ut + (size_t)(b * SEQ + t0) * I_INNER + i;
    const float* gp  = proj + (size_t)(b * SEQ + t0) * 2 * I_INNER + I_INNER + i;
    const float* xp  = xdbl + (size_t)(b * SEQ + t0) * 80;
    float* yp        = y + (size_t)(b * SEQ + t0) * I_INNER + i;
    for (int t = 0; t < CH_LEN; t++) {
        float d = dtp[(size_t)t * I_INNER];
        float u = up[(size_t)t * I_INNER];
        float du = d * u;
        const float* xr = xp + (size_t)t * 80;
        float acc = 0.f;
        #pragma unroll
        for (int n = 0; n < N_STATE; n++) {
            float Bn = xr[48 + n];
            float Cn = xr[64 + n];
            float dA = __expf(d * A[n]);
            h[n] = fmaf(dA, h[n], du * Bn);
            acc = fmaf(h[n], Cn, acc);
        }
        float g = gp[(size_t)t * 2 * I_INNER];
        float sig = 1.f / (1.f + __expf(-g));
        yp[(size_t)t * I_INNER] = tf32r((acc + u * Di) * (g * sig));
    }
}

// ---------------- Logits: out[b,v] = dot(hn[b], embed[v]) ----------------
__global__ void logits_kernel(const float* __restrict__ hn,
                              const float* __restrict__ embed,
                              float* __restrict__ out) {
    __shared__ float sh[BATCH * D_MODEL];
    int tid = threadIdx.x; // 256
    for (int j = tid; j < BATCH * D_MODEL; j += 256) sh[j] = hn[j];
    __syncthreads();
    int warp = tid >> 5, lane = tid & 31;
    int v = blockIdx.x * 8 + warp;
    if (v >= VOCAB) return;
    const float* e = embed + (size_t)v * D_MODEL;
    float a0 = 0.f, a1 = 0.f, a2 = 0.f, a3 = 0.f;
    for (int j = lane; j < D_MODEL; j += 32) {
        float ev = e[j];
        a0 = fmaf(ev, sh[j], a0);
        a1 = fmaf(ev, sh[D_MODEL + j], a1);
        a2 = fmaf(ev, sh[2 * D_MODEL + j], a2);
        a3 = fmaf(ev, sh[3 * D_MODEL + j], a3);
    }
    #pragma unroll
    for (int o = 16; o; o >>= 1) {
        a0 += __shfl_down_sync(0xffffffffu, a0, o);
        a1 += __shfl_down_sync(0xffffffffu, a1, o);
        a2 += __shfl_down_sync(0xffffffffu, a2, o);
        a3 += __shfl_down_sync(0xffffffffu, a3, o);
    }
    if (lane == 0) {
        out[(size_t)0 * VOCAB + v] = a0;
        out[(size_t)1 * VOCAB + v] = a1;
        out[(size_t)2 * VOCAB + v] = a2;
        out[(size_t)3 * VOCAB + v] = a3;
    }
}

// ---------------- Launch ----------------
extern "C" void kernel_launch(void* const* d_in, const int* in_sizes, int n_in,
                              void* d_out, int out_size) {
    const int*   ids       = (const int*)  d_in[0];
    const float* embed     = (const float*)d_in[1];
    const float* norm_w    = (const float*)d_in[2];
    const float* in_proj_w = (const float*)d_in[3];
    const float* conv_w    = (const float*)d_in[4];
    const float* conv_b    = (const float*)d_in[5];
    const float* x_proj_w  = (const float*)d_in[6];
    const float* dt_proj_w = (const float*)d_in[7];
    const float* dt_proj_b = (const float*)d_in[8];
    const float* A_log     = (const float*)d_in[9];
    const float* D_param   = (const float*)d_in[10];
    const float* out_proj_w= (const float*)d_in[11];
    const float* norm_f_w  = (const float*)d_in[12];
    float* out = (float*)d_out;

    float *h, *x, *proj, *ut, *xdbl, *dt, *y, *hn, *wrt, *pA, *hf, *hin;
    cudaGetSymbolAddress((void**)&h,    g_h);
    cudaGetSymbolAddress((void**)&x,    g_x);
    cudaGetSymbolAddress((void**)&proj, g_proj);
    cudaGetSymbolAddress((void**)&ut,   g_ut);
    cudaGetSymbolAddress((void**)&xdbl, g_xdbl);
    cudaGetSymbolAddress((void**)&dt,   g_dt);
    cudaGetSymbolAddress((void**)&y,    g_y);
    cudaGetSymbolAddress((void**)&hn,   g_hn);
    cudaGetSymbolAddress((void**)&wrt,  g_wrt);
    cudaGetSymbolAddress((void**)&pA,   g_pA);
    cudaGetSymbolAddress((void**)&hf,   g_hf);
    cudaGetSymbolAddress((void**)&hin,  g_hin);

    cudaFuncSetAttribute(tgemm<0>, cudaFuncAttributeMaxDynamicSharedMemorySize, TG_SMEM);
    cudaFuncSetAttribute(tgemm<1>, cudaFuncAttributeMaxDynamicSharedMemorySize, TG_SMEM);
    cudaFuncSetAttribute(tgemm<2>, cudaFuncAttributeMaxDynamicSharedMemorySize, TG_SMEM);
    cudaFuncSetAttribute(tgemm<3>, cudaFuncAttributeMaxDynamicSharedMemorySize, TG_SMEM);

    gather_kernel<<<T_TOT, 192>>>(ids, embed, h);

    for (int l = 0; l < L_LAYERS; l++) {
        rmsnorm_kernel<<<T_TOT, 256>>>(h, D_MODEL, norm_w + l * D_MODEL, x, D_MODEL, 1);

        {
            int n = 2 * I_INNER * D_MODEL;
            round_tf32_kernel<<<(n + 255) / 256, 256>>>(
                in_proj_w + (size_t)l * n, wrt, n);
            tgemm<0><<<dim3(24, 64), 256, TG_SMEM>>>(
                x, D_MODEL, wrt, D_MODEL, proj, 2 * I_INNER, 2 * I_INNER, D_MODEL, nullptr);
        }

        conv_silu_kernel<<<(T_TOT * I_INNER + 255) / 256, 256>>>(
            proj, conv_w + (size_t)l * I_INNER * K_CONV, conv_b + (size_t)l * I_INNER, ut);

        {
            int n = 80 * I_INNER;
            round_tf32_kernel<<<(n + 255) / 256, 256>>>(
                x_proj_w + (size_t)l * n, wrt, n);
            tgemm<3><<<dim3(1, 64), 256, TG_SMEM>>>(
                ut, I_INNER, wrt, I_INNER, xdbl, 80, 80, I_INNER, nullptr);
        }

        {
            int n = I_INNER * DT_RANK;
            round_tf32_kernel<<<(n + 255) / 256, 256>>>(
                dt_proj_w + (size_t)l * n, wrt, n);
            tgemm<2><<<dim3(12, 64), 256, TG_SMEM>>>(
                xdbl, 80, wrt, DT_RANK, dt, I_INNER, I_INNER, DT_RANK,
                dt_proj_b + (size_t)l * I_INNER);
        }

        // chunked parallel scan
        const float* Al = A_log + (size_t)l * I_INNER * N_STATE;
        scan_phase1<<<dim3(I_INNER / 128, NCHUNK, BATCH), 128>>>(
            dt, ut, xdbl, Al, pA, hf);
        scan_phase2<<<(BATCH * I_INNER + 127) / 128, 128>>>(pA, hf, hin);
        scan_phase3<<<dim3(I_INNER / 128, NCHUNK, BATCH), 128>>>(
            dt, ut, xdbl, Al, D_param + (size_t)l * I_INNER, proj, hin, y);

        {
            int n = D_MODEL * I_INNER;
            round_tf32_kernel<<<(n + 255) / 256, 256>>>(
                out_proj_w + (size_t)l * n, wrt, n);
            tgemm<1><<<dim3(6, 64), 256, TG_SMEM>>>(
                y, I_INNER, wrt, I_INNER, h, D_MODEL, D_MODEL, I_INNER, nullptr);
        }
    }

    rmsnorm_kernel<<<BATCH, 256>>>(h + (size_t)(SEQ - 1) * D_MODEL,
                                   (long)SEQ * D_MODEL, norm_f_w, hn, D_MODEL, 0);
    logits_kernel<<<(VOCAB + 7) / 8, 256>>>(hn, embed, out);
}